// round 1
// baseline (speedup 1.0000x reference)
#include <cuda_runtime.h>

#define Hdim 512
#define Ddim 64
#define Mrows 32
#define NTHREADS 256
#define ZSTRIDE 34
#define BMAX 65536

// ---- device scratch (static allocation; no cudaMalloc allowed) ----
static __device__ float g_WzT[3][Hdim * Hdim];   // Wz1..3 transposed [k][h]
static __device__ float g_WzT0[Ddim * Hdim];     // Wz0 transposed [d][h]
static __device__ float g_WxT[3][Ddim * Hdim];   // Wx0..2 transposed [d][h]
static __device__ float g_s[3][(size_t)BMAX * Hdim];  // sigmoid(pre1..pre3)

// ---------------------------------------------------------------------------
// Prologue: build transposed weight copies (write-coalesced; idempotent).
// ---------------------------------------------------------------------------
__global__ void prep_kernel(
    const float* __restrict__ Wz0, const float* __restrict__ Wz1,
    const float* __restrict__ Wz2, const float* __restrict__ Wz3,
    const float* __restrict__ Wx0, const float* __restrict__ Wx1,
    const float* __restrict__ Wx2)
{
    for (int i = blockIdx.x * blockDim.x + threadIdx.x; i < Hdim * Hdim;
         i += gridDim.x * blockDim.x) {
        int k = i >> 9;            // row of transposed = column of original
        int h = i & (Hdim - 1);
        g_WzT[0][i] = Wz1[h * Hdim + k];
        g_WzT[1][i] = Wz2[h * Hdim + k];
        g_WzT[2][i] = Wz3[h * Hdim + k];
        if (i < Ddim * Hdim) {
            int d = i >> 9;        // 0..63
            g_WzT0[i]   = Wz0[h * Ddim + d];
            g_WxT[0][i] = Wx0[h * Ddim + d];
            g_WxT[1][i] = Wx1[h * Ddim + d];
            g_WxT[2][i] = Wx2[h * Ddim + d];
        }
    }
}

// ---------------------------------------------------------------------------
// Helpers
// ---------------------------------------------------------------------------

// stable softplus + sigmoid
__device__ __forceinline__ void act(float p, float& z, float& s)
{
    float e = __expf(-fabsf(p));          // e in [0,1]
    float r = 1.0f / (1.0f + e);
    z = fmaxf(p, 0.0f) + log1pf(e);
    s = (p >= 0.0f) ? r : e * r;
}

// acc[m][j] += sum_k WT[k][t + 256*j] * zT[k][m]
// WT: [K][512] row-major (stride Hdim). zT: SMEM [K][ZSTRIDE].
__device__ __forceinline__ void gemm_accum(
    const float* __restrict__ WT, int K, const float* zT, int t,
    float* acc0, float* acc1)
{
    #pragma unroll 2
    for (int k = 0; k < K; k++) {
        float w0 = __ldg(WT + (size_t)k * Hdim + t);
        float w1 = __ldg(WT + (size_t)k * Hdim + t + 256);
        const float2* zrow = reinterpret_cast<const float2*>(zT + k * ZSTRIDE);
        #pragma unroll
        for (int c = 0; c < Mrows / 2; c++) {
            float2 a = zrow[c];                 // broadcast LDS (all lanes same addr)
            acc0[2 * c]     = fmaf(a.x, w0, acc0[2 * c]);
            acc0[2 * c + 1] = fmaf(a.y, w0, acc0[2 * c + 1]);
            acc1[2 * c]     = fmaf(a.x, w1, acc1[2 * c]);
            acc1[2 * c + 1] = fmaf(a.y, w1, acc1[2 * c + 1]);
        }
    }
}

// forward epilogue for layers 1..3: z -> zdst (SMEM, transposed), s -> global
__device__ __forceinline__ void fwd_epi(
    const float* acc0, const float* acc1, const float* __restrict__ b,
    float* zdst, float* __restrict__ sdst, int t, int rowbase)
{
    float b0 = __ldg(b + t), b1 = __ldg(b + t + 256);
    #pragma unroll
    for (int m = 0; m < Mrows; m++) {
        float z0, s0, z1, s1;
        act(acc0[m] + b0, z0, s0);
        act(acc1[m] + b1, z1, s1);
        zdst[t * ZSTRIDE + m]         = z0;
        zdst[(t + 256) * ZSTRIDE + m] = z1;
        size_t base = (size_t)(rowbase + m) * Hdim;
        sdst[base + t]       = s0;       // coalesced across lanes
        sdst[base + t + 256] = s1;
    }
}

// backward epilogue: d = s * acc -> ddst (SMEM transposed)
__device__ __forceinline__ void bwd_epi(
    const float* acc0, const float* acc1, const float* __restrict__ ssrc,
    float* ddst, int t, int rowbase)
{
    #pragma unroll
    for (int m = 0; m < Mrows; m++) {
        size_t base = (size_t)(rowbase + m) * Hdim;
        float s0 = __ldg(ssrc + base + t);
        float s1 = __ldg(ssrc + base + t + 256);
        ddst[t * ZSTRIDE + m]         = s0 * acc0[m];
        ddst[(t + 256) * ZSTRIDE + m] = s1 * acc1[m];
    }
}

// grad[m][d] += sum_h W[h][d] * dT[h][m]   (W: [512][64] row-major)
// thread covers d-pair = 2*(t&31), rows mg..mg+3 with mg = (t>>5)*4
__device__ __forceinline__ void gmatvec(
    const float* __restrict__ W, const float* dT, int t, float* gacc)
{
    const int dp = (t & 31) * 2;
    const int mg = (t >> 5) * 4;
    #pragma unroll 4
    for (int h = 0; h < Hdim; h++) {
        float2 w   = __ldg(reinterpret_cast<const float2*>(W + h * Ddim + dp));
        float2 a01 = *reinterpret_cast<const float2*>(dT + h * ZSTRIDE + mg);
        float2 a23 = *reinterpret_cast<const float2*>(dT + h * ZSTRIDE + mg + 2);
        gacc[0] = fmaf(a01.x, w.x, gacc[0]);
        gacc[1] = fmaf(a01.x, w.y, gacc[1]);
        gacc[2] = fmaf(a01.y, w.x, gacc[2]);
        gacc[3] = fmaf(a01.y, w.y, gacc[3]);
        gacc[4] = fmaf(a23.x, w.x, gacc[4]);
        gacc[5] = fmaf(a23.x, w.y, gacc[5]);
        gacc[6] = fmaf(a23.y, w.x, gacc[6]);
        gacc[7] = fmaf(a23.y, w.y, gacc[7]);
    }
}

// ---------------------------------------------------------------------------
// Fused ICNN forward + backward, 32 samples per CTA.
// ---------------------------------------------------------------------------
__global__ void __launch_bounds__(NTHREADS, 1) icnn_kernel(
    const float* __restrict__ state,
    const float* __restrict__ bz0,
    const float* __restrict__ bx0,
    const float* __restrict__ bx1,
    const float* __restrict__ bx2,
    const float* __restrict__ WzL,
    const float* __restrict__ WxL,
    const float* __restrict__ Wz0,
    const float* __restrict__ Wz1,
    const float* __restrict__ Wz2,
    const float* __restrict__ Wz3,
    const float* __restrict__ Wx0,
    const float* __restrict__ Wx1,
    const float* __restrict__ Wx2,
    float* __restrict__ out)
{
    extern __shared__ float smem[];
    float* bufA = smem;                         // [512][ZSTRIDE]
    float* bufB = smem + Hdim * ZSTRIDE;        // [512][ZSTRIDE]
    float* xT   = smem + 2 * Hdim * ZSTRIDE;    // [64][ZSTRIDE]

    const int t = threadIdx.x;
    const int rowbase = blockIdx.x * Mrows;

    // load x tile (x = state - 1), transposed [d][m]
    #pragma unroll
    for (int i = 0; i < (Mrows * Ddim) / NTHREADS; i++) {
        int idx = t + i * NTHREADS;
        int m = idx >> 6;
        int d = idx & 63;
        xT[d * ZSTRIDE + m] = state[(size_t)(rowbase + m) * Ddim + d] - 1.0f;
    }
    __syncthreads();

    float acc0[Mrows], acc1[Mrows];

    // ---------------- Layer 1: pre1 = Wz0 x + bz0 ----------------
    #pragma unroll
    for (int m = 0; m < Mrows; m++) { acc0[m] = 0.f; acc1[m] = 0.f; }
    gemm_accum(g_WzT0, Ddim, xT, t, acc0, acc1);
    fwd_epi(acc0, acc1, bz0, bufA, g_s[0], t, rowbase);
    __syncthreads();

    // ---------------- Layers 2..4 ----------------
    {
        const float* WzTl[3] = { g_WzT[0], g_WzT[1], g_WzT[2] };
        const float* WxTl[3] = { g_WxT[0], g_WxT[1], g_WxT[2] };
        const float* bxl[3]  = { bx0, bx1, bx2 };
        float* bufs[2] = { bufA, bufB };
        for (int l = 0; l < 3; l++) {
            const float* src = bufs[l & 1];
            float* dst = bufs[(l & 1) ^ 1];
            #pragma unroll
            for (int m = 0; m < Mrows; m++) { acc0[m] = 0.f; acc1[m] = 0.f; }
            gemm_accum(WzTl[l], Hdim, src, t, acc0, acc1);   // z-path
            gemm_accum(WxTl[l], Ddim, xT,  t, acc0, acc1);   // x-skip path
            if (l < 2) {
                fwd_epi(acc0, acc1, bxl[l], dst, g_s[l + 1], t, rowbase);
            } else {
                // layer 4: d4T[h][m] = WzL[h] * sigmoid(pre4)  (s4 never stored)
                float b0 = __ldg(bxl[2] + t), b1 = __ldg(bxl[2] + t + 256);
                float wl0 = __ldg(WzL + t),   wl1 = __ldg(WzL + t + 256);
                #pragma unroll
                for (int m = 0; m < Mrows; m++) {
                    float z0, s0, z1, s1;
                    act(acc0[m] + b0, z0, s0);
                    act(acc1[m] + b1, z1, s1);
                    dst[t * ZSTRIDE + m]         = wl0 * s0;
                    dst[(t + 256) * ZSTRIDE + m] = wl1 * s1;
                }
            }
            __syncthreads();
        }
    }

    // ---------------- Backward ----------------
    float gacc[8];
    #pragma unroll
    for (int i = 0; i < 8; i++) gacc[i] = 0.f;
    {
        const float* WzB[3] = { Wz3, Wz2, Wz1 };   // transposed-apply = original layout
        const float* WxG[3] = { Wx2, Wx1, Wx0 };
        float* bufs[2] = { bufB, bufA };           // d4T sits in bufB after forward
        for (int j = 0; j < 3; j++) {
            const float* src = bufs[j & 1];        // d_{4-j}T
            float* dst = bufs[(j & 1) ^ 1];
            gmatvec(WxG[j], src, t, gacc);         // grad += Wx^T d (reads src only)
            #pragma unroll
            for (int m = 0; m < Mrows; m++) { acc0[m] = 0.f; acc1[m] = 0.f; }
            gemm_accum(WzB[j], Hdim, src, t, acc0, acc1);   // t = Wz^T d
            bwd_epi(acc0, acc1, g_s[2 - j], dst, t, rowbase);
            __syncthreads();
        }
        gmatvec(Wz0, bufA, t, gacc);               // grad += Wz0^T d1  (d1T in bufA)
    }

    // ---------------- Output: grad + WxL ----------------
    {
        const int dp = (t & 31) * 2;
        const int mg = (t >> 5) * 4;
        float2 wxl = __ldg(reinterpret_cast<const float2*>(WxL + dp));
        #pragma unroll
        for (int i = 0; i < 4; i++) {
            float2 r;
            r.x = gacc[2 * i]     + wxl.x;
            r.y = gacc[2 * i + 1] + wxl.y;
            *reinterpret_cast<float2*>(out + (size_t)(rowbase + mg + i) * Ddim + dp) = r;
        }
    }
}

// ---------------------------------------------------------------------------
extern "C" void kernel_launch(void* const* d_in, const int* in_sizes, int n_in,
                              void* d_out, int out_size)
{
    const float* state = (const float*)d_in[0];
    const float* Wz0   = (const float*)d_in[1];
    const float* bz0   = (const float*)d_in[2];
    const float* Wz1   = (const float*)d_in[3];
    const float* Wz2   = (const float*)d_in[4];
    const float* Wz3   = (const float*)d_in[5];
    const float* WzL   = (const float*)d_in[6];
    const float* Wx0   = (const float*)d_in[7];
    const float* bx0   = (const float*)d_in[8];
    const float* Wx1   = (const float*)d_in[9];
    const float* bx1   = (const float*)d_in[10];
    const float* Wx2   = (const float*)d_in[11];
    const float* bx2   = (const float*)d_in[12];
    const float* WxL   = (const float*)d_in[13];
    float* out = (float*)d_out;

    int B = in_sizes[0] / Ddim;   // 65536
    int smem_bytes = (2 * Hdim + Ddim) * ZSTRIDE * (int)sizeof(float);  // ~144.5 KB

    cudaFuncSetAttribute(icnn_kernel, cudaFuncAttributeMaxDynamicSharedMemorySize,
                         smem_bytes);

    prep_kernel<<<256, 256>>>(Wz0, Wz1, Wz2, Wz3, Wx0, Wx1, Wx2);
    icnn_kernel<<<B / Mrows, NTHREADS, smem_bytes>>>(
        state, bz0, bx0, bx1, bx2, WzL, WxL,
        Wz0, Wz1, Wz2, Wz3, Wx0, Wx1, Wx2, out);
}

// round 2
// speedup vs baseline: 1.6518x; 1.6518x over previous
#include <cuda_runtime.h>
#include <cstdint>

#define Hdim 512
#define Ddim 64
#define Mrows 32
#define NT 256
#define S 36                      // SMEM row stride (floats): 144B, 16B-aligned
#define BMAX 65536

// ---- device scratch (no cudaMalloc allowed) ----
static __device__ float g_WzT[3][Hdim * Hdim];   // Wz1..3 transposed [k][h]
static __device__ float g_WzT0[Ddim * Hdim];     // Wz0 transposed [d][h]
static __device__ float g_WxT[3][Ddim * Hdim];   // Wx0..2 transposed [d][h]
static __device__ float g_s[3][(size_t)BMAX * Hdim];  // sigmoid(pre1..pre3)

// ---------------------------------------------------------------------------
__global__ void prep_kernel(
    const float* __restrict__ Wz0, const float* __restrict__ Wz1,
    const float* __restrict__ Wz2, const float* __restrict__ Wz3,
    const float* __restrict__ Wx0, const float* __restrict__ Wx1,
    const float* __restrict__ Wx2)
{
    for (int i = blockIdx.x * blockDim.x + threadIdx.x; i < Hdim * Hdim;
         i += gridDim.x * blockDim.x) {
        int k = i >> 9;
        int h = i & (Hdim - 1);
        g_WzT[0][i] = Wz1[h * Hdim + k];
        g_WzT[1][i] = Wz2[h * Hdim + k];
        g_WzT[2][i] = Wz3[h * Hdim + k];
        if (i < Ddim * Hdim) {
            int d = i >> 9;
            g_WzT0[i]   = Wz0[h * Ddim + d];
            g_WxT[0][i] = Wx0[h * Ddim + d];
            g_WxT[1][i] = Wx1[h * Ddim + d];
            g_WxT[2][i] = Wx2[h * Ddim + d];
        }
    }
}

// ---------------------------------------------------------------------------
// f32x2 packed-FMA helpers (FFMA2 — only reachable via PTX fma.rn.f32x2)
// ---------------------------------------------------------------------------
__device__ __forceinline__ void ffma2(uint64_t& acc, uint64_t a, uint64_t b)
{
    asm("fma.rn.f32x2 %0, %1, %2, %0;" : "+l"(acc) : "l"(a), "l"(b));
}
__device__ __forceinline__ uint64_t pk(float x, float y)
{
    uint64_t r; asm("mov.b64 %0, {%1, %2};" : "=l"(r) : "f"(x), "f"(y)); return r;
}
__device__ __forceinline__ uint64_t dup(float x)
{
    uint64_t r; asm("mov.b64 %0, {%1, %1};" : "=l"(r) : "f"(x)); return r;
}
__device__ __forceinline__ void upk(uint64_t v, float& x, float& y)
{
    asm("mov.b64 {%0, %1}, %2;" : "=f"(x), "=f"(y) : "l"(v));
}

// stable softplus + sigmoid
__device__ __forceinline__ void act(float p, float& z, float& s)
{
    float e = __expf(-fabsf(p));
    float r = 1.0f / (1.0f + e);
    z = fmaxf(p, 0.0f) + log1pf(e);
    s = (p >= 0.0f) ? r : e * r;
}

// ---------------------------------------------------------------------------
// 8x8 register-blocked GEMM core with packed f32x2 accumulation.
// acc[m*4+np] = f32x2 pair over cols (n0+2np, n0+2np+1), rows m0+m.
// WT: [K][512] row-major global. zT: SMEM [K][S].
// ---------------------------------------------------------------------------
template <int K>
__device__ __forceinline__ void gemm8x8(
    const float* __restrict__ WT, const float* zT, int n0, int m0,
    uint64_t* acc)
{
    #pragma unroll 4
    for (int k = 0; k < K; k++) {
        float4 w0 = __ldg((const float4*)(WT + (size_t)k * Hdim + n0));
        float4 w1 = __ldg((const float4*)(WT + (size_t)k * Hdim + n0 + 4));
        uint64_t b0 = pk(w0.x, w0.y), b1 = pk(w0.z, w0.w);
        uint64_t b2 = pk(w1.x, w1.y), b3 = pk(w1.z, w1.w);
        float4 a0 = *(const float4*)(zT + k * S + m0);
        float4 a1 = *(const float4*)(zT + k * S + m0 + 4);
        float av[8] = { a0.x, a0.y, a0.z, a0.w, a1.x, a1.y, a1.z, a1.w };
        #pragma unroll
        for (int m = 0; m < 8; m++) {
            uint64_t ad = dup(av[m]);
            ffma2(acc[m * 4 + 0], ad, b0);
            ffma2(acc[m * 4 + 1], ad, b1);
            ffma2(acc[m * 4 + 2], ad, b2);
            ffma2(acc[m * 4 + 3], ad, b3);
        }
    }
}

// grad[m][d] += sum_h W[h][d] * dT[h][m]   (W: [512][64] row-major)
// thread covers d-pair dp=(t&31)*2, rows mg..mg+3, mg=(t>>5)*4.
// gacc: 4 f32x2 pairs over (dp, dp+1) for 4 rows.
__device__ __forceinline__ void gmatvec(
    const float* __restrict__ W, const float* dT, int t, uint64_t* gacc)
{
    const int dp = (t & 31) * 2;
    const int mg = (t >> 5) * 4;
    #pragma unroll 4
    for (int h = 0; h < Hdim; h++) {
        float2 w   = __ldg((const float2*)(W + h * Ddim + dp));
        float2 a01 = *(const float2*)(dT + h * S + mg);
        float2 a23 = *(const float2*)(dT + h * S + mg + 2);
        uint64_t wp = pk(w.x, w.y);
        ffma2(gacc[0], dup(a01.x), wp);
        ffma2(gacc[1], dup(a01.y), wp);
        ffma2(gacc[2], dup(a23.x), wp);
        ffma2(gacc[3], dup(a23.y), wp);
    }
}

// ---------------------------------------------------------------------------
// Fused ICNN forward + backward, 32 samples / CTA, 8x8 thread tiles.
// ---------------------------------------------------------------------------
__global__ void __launch_bounds__(NT, 1) icnn_kernel(
    const float* __restrict__ state,
    const float* __restrict__ bz0,
    const float* __restrict__ bx0,
    const float* __restrict__ bx1,
    const float* __restrict__ bx2,
    const float* __restrict__ WzL,
    const float* __restrict__ WxL,
    const float* __restrict__ Wz0,
    const float* __restrict__ Wz1,
    const float* __restrict__ Wz2,
    const float* __restrict__ Wz3,
    const float* __restrict__ Wx0,
    const float* __restrict__ Wx1,
    const float* __restrict__ Wx2,
    float* __restrict__ out)
{
    extern __shared__ float smem[];
    float* bufA = smem;                       // [512][S]
    float* bufB = smem + Hdim * S;            // [512][S]
    float* xT   = smem + 2 * Hdim * S;        // [64][S]

    const int t = threadIdx.x;
    const int tcol = t & 63;                  // warp-contiguous -> coalesced LDG
    const int trow = t >> 6;                  // constant within a warp -> LDS broadcast
    const int n0 = tcol << 3;
    const int m0 = trow << 3;
    const int rowbase = blockIdx.x * Mrows;

    // load x tile (x = state - 1), transposed [d][m]
    #pragma unroll
    for (int i = 0; i < (Mrows * Ddim) / NT; i++) {
        int idx = t + i * NT;
        int m = idx >> 6;
        int d = idx & 63;
        xT[d * S + m] = state[(size_t)(rowbase + m) * Ddim + d] - 1.0f;
    }
    __syncthreads();

    uint64_t acc[32];

    // ---------------- Layer 1: pre1 = Wz0 x + bz0 ----------------
    #pragma unroll
    for (int i = 0; i < 32; i++) acc[i] = 0ull;
    gemm8x8<Ddim>(g_WzT0, xT, n0, m0, acc);
    {
        float4 bb0 = __ldg((const float4*)(bz0 + n0));
        float4 bb1 = __ldg((const float4*)(bz0 + n0 + 4));
        float bn[8] = { bb0.x, bb0.y, bb0.z, bb0.w, bb1.x, bb1.y, bb1.z, bb1.w };
        #pragma unroll
        for (int m = 0; m < 8; m++) {
            float z[8], sg[8];
            #pragma unroll
            for (int np = 0; np < 4; np++) {
                float p0, p1; upk(acc[m * 4 + np], p0, p1);
                act(p0 + bn[2 * np],     z[2 * np],     sg[2 * np]);
                act(p1 + bn[2 * np + 1], z[2 * np + 1], sg[2 * np + 1]);
            }
            int mm = m0 + m;
            #pragma unroll
            for (int j = 0; j < 8; j++) {         // rotate to spread banks
                int jj = (j + tcol) & 7;
                bufA[(n0 + jj) * S + mm] = z[jj];
            }
            size_t base = (size_t)(rowbase + mm) * Hdim + n0;
            *(float4*)(g_s[0] + base)     = make_float4(sg[0], sg[1], sg[2], sg[3]);
            *(float4*)(g_s[0] + base + 4) = make_float4(sg[4], sg[5], sg[6], sg[7]);
        }
    }
    __syncthreads();

    // ---------------- Layers 2..4 ----------------
    {
        float* bufs[2] = { bufA, bufB };
        #pragma unroll 1
        for (int l = 0; l < 3; l++) {
            const float* WzTl = (l == 0) ? g_WzT[0] : (l == 1) ? g_WzT[1] : g_WzT[2];
            const float* WxTl = (l == 0) ? g_WxT[0] : (l == 1) ? g_WxT[1] : g_WxT[2];
            const float* bl   = (l == 0) ? bx0 : (l == 1) ? bx1 : bx2;
            const float* src = bufs[l & 1];
            float* dst = bufs[(l & 1) ^ 1];
            #pragma unroll
            for (int i = 0; i < 32; i++) acc[i] = 0ull;
            gemm8x8<Hdim>(WzTl, src, n0, m0, acc);
            gemm8x8<Ddim>(WxTl, xT,  n0, m0, acc);

            float4 bb0 = __ldg((const float4*)(bl + n0));
            float4 bb1 = __ldg((const float4*)(bl + n0 + 4));
            float bn[8] = { bb0.x, bb0.y, bb0.z, bb0.w, bb1.x, bb1.y, bb1.z, bb1.w };

            if (l < 2) {
                float* sdst = g_s[l + 1];
                #pragma unroll
                for (int m = 0; m < 8; m++) {
                    float z[8], sg[8];
                    #pragma unroll
                    for (int np = 0; np < 4; np++) {
                        float p0, p1; upk(acc[m * 4 + np], p0, p1);
                        act(p0 + bn[2 * np],     z[2 * np],     sg[2 * np]);
                        act(p1 + bn[2 * np + 1], z[2 * np + 1], sg[2 * np + 1]);
                    }
                    int mm = m0 + m;
                    #pragma unroll
                    for (int j = 0; j < 8; j++) {
                        int jj = (j + tcol) & 7;
                        dst[(n0 + jj) * S + mm] = z[jj];
                    }
                    size_t base = (size_t)(rowbase + mm) * Hdim + n0;
                    *(float4*)(sdst + base)     = make_float4(sg[0], sg[1], sg[2], sg[3]);
                    *(float4*)(sdst + base + 4) = make_float4(sg[4], sg[5], sg[6], sg[7]);
                }
            } else {
                // layer 4: d4T[n][m] = WzL[n] * sigmoid(pre4)
                float4 wl0 = __ldg((const float4*)(WzL + n0));
                float4 wl1 = __ldg((const float4*)(WzL + n0 + 4));
                float wl[8] = { wl0.x, wl0.y, wl0.z, wl0.w, wl1.x, wl1.y, wl1.z, wl1.w };
                #pragma unroll
                for (int m = 0; m < 8; m++) {
                    float dv[8];
                    #pragma unroll
                    for (int np = 0; np < 4; np++) {
                        float p0, p1; upk(acc[m * 4 + np], p0, p1);
                        float zt, s0, s1;
                        act(p0 + bn[2 * np],     zt, s0);
                        act(p1 + bn[2 * np + 1], zt, s1);
                        dv[2 * np]     = wl[2 * np] * s0;
                        dv[2 * np + 1] = wl[2 * np + 1] * s1;
                    }
                    int mm = m0 + m;
                    #pragma unroll
                    for (int j = 0; j < 8; j++) {
                        int jj = (j + tcol) & 7;
                        dst[(n0 + jj) * S + mm] = dv[jj];
                    }
                }
            }
            __syncthreads();
        }
    }

    // ---------------- Backward ----------------
    uint64_t gacc[4];
    #pragma unroll
    for (int i = 0; i < 4; i++) gacc[i] = 0ull;
    {
        float* bufs[2] = { bufB, bufA };       // d4T sits in bufB
        #pragma unroll 1
        for (int j = 0; j < 3; j++) {
            const float* WzB = (j == 0) ? Wz3 : (j == 1) ? Wz2 : Wz1;
            const float* WxG = (j == 0) ? Wx2 : (j == 1) ? Wx1 : Wx0;
            const float* ssrc = g_s[2 - j];
            const float* src = bufs[j & 1];
            float* dst = bufs[(j & 1) ^ 1];

            gmatvec(WxG, src, t, gacc);        // grad += Wx^T d

            #pragma unroll
            for (int i = 0; i < 32; i++) acc[i] = 0ull;
            gemm8x8<Hdim>(WzB, src, n0, m0, acc);   // t = Wz^T d (orig layout = transposed-apply)

            #pragma unroll
            for (int m = 0; m < 8; m++) {
                int mm = m0 + m;
                size_t base = (size_t)(rowbase + mm) * Hdim + n0;
                float4 s0 = __ldg((const float4*)(ssrc + base));
                float4 s1 = __ldg((const float4*)(ssrc + base + 4));
                float sv[8] = { s0.x, s0.y, s0.z, s0.w, s1.x, s1.y, s1.z, s1.w };
                float dv[8];
                #pragma unroll
                for (int np = 0; np < 4; np++) {
                    float p0, p1; upk(acc[m * 4 + np], p0, p1);
                    dv[2 * np]     = sv[2 * np] * p0;
                    dv[2 * np + 1] = sv[2 * np + 1] * p1;
                }
                #pragma unroll
                for (int jj0 = 0; jj0 < 8; jj0++) {
                    int jj = (jj0 + tcol) & 7;
                    dst[(n0 + jj) * S + mm] = dv[jj];
                }
            }
            __syncthreads();
        }
        gmatvec(Wz0, bufA, t, gacc);           // grad += Wz0^T d1 (d1T in bufA)
    }

    // ---------------- Output: grad + WxL ----------------
    {
        const int dp = (t & 31) * 2;
        const int mg = (t >> 5) * 4;
        float2 wxl = __ldg((const float2*)(WxL + dp));
        #pragma unroll
        for (int i = 0; i < 4; i++) {
            float g0, g1; upk(gacc[i], g0, g1);
            float2 r; r.x = g0 + wxl.x; r.y = g1 + wxl.y;
            *(float2*)(out + (size_t)(rowbase + mg + i) * Ddim + dp) = r;
        }
    }
}

// ---------------------------------------------------------------------------
extern "C" void kernel_launch(void* const* d_in, const int* in_sizes, int n_in,
                              void* d_out, int out_size)
{
    const float* state = (const float*)d_in[0];
    const float* Wz0   = (const float*)d_in[1];
    const float* bz0   = (const float*)d_in[2];
    const float* Wz1   = (const float*)d_in[3];
    const float* Wz2   = (const float*)d_in[4];
    const float* Wz3   = (const float*)d_in[5];
    const float* WzL   = (const float*)d_in[6];
    const float* Wx0   = (const float*)d_in[7];
    const float* bx0   = (const float*)d_in[8];
    const float* Wx1   = (const float*)d_in[9];
    const float* bx1   = (const float*)d_in[10];
    const float* Wx2   = (const float*)d_in[11];
    const float* bx2   = (const float*)d_in[12];
    const float* WxL   = (const float*)d_in[13];
    float* out = (float*)d_out;

    int B = in_sizes[0] / Ddim;
    int smem_bytes = (2 * Hdim + Ddim) * S * (int)sizeof(float);  // ~153 KB

    cudaFuncSetAttribute(icnn_kernel, cudaFuncAttributeMaxDynamicSharedMemorySize,
                         smem_bytes);

    prep_kernel<<<256, 256>>>(Wz0, Wz1, Wz2, Wz3, Wx0, Wx1, Wx2);
    icnn_kernel<<<B / Mrows, NT, smem_bytes>>>(
        state, bz0, bx0, bx1, bx2, WzL, WxL,
        Wz0, Wz1, Wz2, Wz3, Wx0, Wx1, Wx2, out);
}